// round 12
// baseline (speedup 1.0000x reference)
#include <cuda_runtime.h>
#include <stdint.h>

#define N_TOKENS 131072
#define D_MODEL  512
#define PATHS    16
#define CAP      16384                 // 2 * N / P
#define D4       (D_MODEL / 4)         // 128 float4 per row
#define ROWS     (PATHS * CAP)         // 262144 output rows

#define TPB      512                   // 16 warps
#define NWARP    16
#define NB_R     256                   // route blocks (bid < NB_R): 256*512 = N_TOKENS
#define GROWS_PB 16                    // output rows per block (one per warp)
#define GRID_G   (ROWS / GROWS_PB)     // 16384 blocks

// ---- scratch (no allocations allowed; zero-initialized at load) ----
__device__ int      g_cnt[PATHS];          // per-path count, clamped to CAP
__device__ int      g_slot[ROWS];          // slot -> token gather map
__device__ int      g_hist[PATHS * NB_R];  // per-(path, block) counts  [path][block]
__device__ unsigned g_arrive;              // route-internal barrier counter
__device__ unsigned g_done;                // route completion counter
__device__ unsigned g_flag1;               // counts ready  (zero rows may go)
__device__ unsigned g_flag2;               // slot map ready (copy rows may go)
__device__ unsigned g_exit;                // kernel exit counter (self-clean)

__device__ __forceinline__ unsigned vload(const unsigned* p) {
    return *(volatile const unsigned*)p;
}

__global__ __launch_bounds__(TPB, 4) void k_fused(const float* __restrict__ score,
                                                  const float4* __restrict__ in4,
                                                  float4* __restrict__ out4) {
    __shared__ int sh_cnt[NWARP][PATHS];
    __shared__ int sh_wexcl[NWARP][PATHS];
    __shared__ int sh_excl[PATHS];
    __shared__ int sh_run[NWARP][PATHS];
    __shared__ int sh_last;
    const int tid = threadIdx.x, w = tid >> 5, lane = tid & 31, bid = blockIdx.x;

    // ================= ROUTE PHASE (blocks 0..NB_R-1 only) =================
    if (bid < NB_R) {
        const int tok = bid * TPB + tid;               // one token per thread

        // argmax + per-warp per-path counts
        if (lane < PATHS) sh_cnt[w][lane] = 0;
        __syncwarp();
        int best;
        {
            const float4* sc = (const float4*)(score + (size_t)tok * PATHS);
            float4 a = __ldcs(sc), b = __ldcs(sc + 1), c = __ldcs(sc + 2), d = __ldcs(sc + 3);
            float v[16] = {a.x,a.y,a.z,a.w, b.x,b.y,b.z,b.w,
                           c.x,c.y,c.z,c.w, d.x,d.y,d.z,d.w};
            best = 0; float bv = v[0];
            #pragma unroll
            for (int p = 1; p < 16; p++) if (v[p] > bv) { bv = v[p]; best = p; }  // first-max
            unsigned m = __match_any_sync(0xffffffffu, best);
            if ((__ffs(m) - 1) == lane) sh_cnt[w][best] += __popc(m);
        }
        __syncthreads();

        // block scan over 16 warps + publish block aggregate (writer fences)
        if (w == 0 && lane < PATHS) {
            int run = 0;
            #pragma unroll
            for (int ww = 0; ww < NWARP; ww++) { int v = sh_cnt[ww][lane]; sh_wexcl[ww][lane] = run; run += v; }
            g_hist[lane * NB_R + bid] = run;           // [path][block]
            __threadfence();
        }
        __syncthreads();

        // resident barrier over route blocks (plain spin — backoff proven harmful)
        if (tid == 0) {
            atomicAdd(&g_arrive, 1u);
            while (vload(&g_arrive) < (unsigned)NB_R) { }
        }
        __syncthreads();

        // bulk prefix: warp w owns path w; read full hist row
        {
            int excl = 0, tot = 0;
            #pragma unroll
            for (int s = 0; s < NB_R / 32; s++) {
                const int j = s * 32 + lane;
                const int v = g_hist[w * NB_R + j];
                tot += v;
                if (j < bid) excl += v;
            }
            excl = __reduce_add_sync(0xffffffffu, excl);
            tot  = __reduce_add_sync(0xffffffffu, tot);
            if (lane == 0) {
                sh_excl[w] = excl;
                if (bid == 0) { g_cnt[w] = tot < CAP ? tot : CAP; __threadfence(); }
            }
        }
        __syncthreads();

        // counts are now globally valid -> release the zero-row stream early
        if (bid == 0 && tid == 0) atomicExch(&g_flag1, 1u);

        // order-preserving rank -> slot map
        if (lane < PATHS) sh_run[w][lane] = sh_excl[lane] + sh_wexcl[w][lane];
        __syncwarp();
        {
            unsigned m = __match_any_sync(0xffffffffu, best);
            const int rank = __popc(m & ((1u << lane) - 1u));
            const int pos = sh_run[w][best] + rank;
            if (pos < CAP) g_slot[best * CAP + pos] = tok;
        }

        // release copy rows: every writing thread fences, last block raises flag2
        __threadfence();
        __syncthreads();
        if (tid == 0) {
            if (atomicAdd(&g_done, 1u) == (unsigned)(NB_R - 1))
                atomicExch(&g_flag2, 1u);
        }
    }

    // ================= GATE 1: counts (cheap, raised early) =================
    if (tid == 0) { while (vload(&g_flag1) == 0u) { } }
    __syncthreads();
    __threadfence();

    const int r0 = bid * GROWS_PB;                     // block's first output row
    const int p  = r0 >> 14;                           // path (uniform per block)
    const int jb = r0 & (CAP - 1);                     // first j in block
    const int cnt = g_cnt[p];

    // ======= blocks containing copy rows must wait for the slot map =======
    if (jb < cnt) {
        if (tid == 0) { while (vload(&g_flag2) == 0u) { } }
        __syncthreads();
        __threadfence();
    }

    // ================= OUTPUT PHASE (one row per warp) =================
    {
        const int r = r0 + w;
        const int j = jb + w;
        float4 v0 = make_float4(0.f,0.f,0.f,0.f);
        float4 v1 = v0, v2 = v0, v3 = v0;
        if (j < cnt) {
            const float4* src = in4 + (size_t)g_slot[r] * D4 + lane;
            v0 = src[0];
            v1 = src[32];
            v2 = src[64];
            v3 = src[96];
        }
        float4* dst = out4 + (size_t)r * D4 + lane;
        dst[0]  = v0;
        dst[32] = v1;
        dst[64] = v2;
        dst[96] = v3;
    }

    // ================= SELF-CLEAN (deterministic graph replay) =================
    __syncthreads();
    if (tid == 0) sh_last = (atomicAdd(&g_exit, 1u) == (unsigned)(GRID_G - 1));
    __syncthreads();
    if (sh_last && tid == 0) { g_arrive = 0; g_done = 0; g_flag1 = 0; g_flag2 = 0; g_exit = 0; }
}

extern "C" void kernel_launch(void* const* d_in, const int* in_sizes, int n_in,
                              void* d_out, int out_size) {
    const float* inputs = (const float*)d_in[0];
    const float* score  = (const float*)d_in[1];
    if (in_sizes[0] == N_TOKENS * PATHS) {   // defensive: identify by element count
        inputs = (const float*)d_in[1];
        score  = (const float*)d_in[0];
    }
    k_fused<<<GRID_G, TPB>>>(score, (const float4*)inputs, (float4*)d_out);
}

// round 13
// speedup vs baseline: 1.1307x; 1.1307x over previous
#include <cuda_runtime.h>
#include <stdint.h>

#define N_TOKENS 131072
#define D_MODEL  512
#define PATHS    16
#define CAP      16384                 // 2 * N / P
#define D4       (D_MODEL / 4)         // 128 float4 per row
#define ROWS     (PATHS * CAP)         // 262144 output rows

#define NB       256                   // route blocks (all co-resident: 512thr)
#define TPB      512                   // 16 warps, one token per thread
#define NWARP    16

// ---- scratch (no allocations allowed; zero-initialized at load) ----
__device__ int      g_cnt[PATHS];          // per-path count, clamped to CAP
__device__ int      g_slot[ROWS];          // slot -> token gather map
__device__ int      g_hist[PATHS * NB];    // per-(path, block) counts  [path][block]
__device__ unsigned g_arrive;              // grid barrier counter (self-resets)
__device__ unsigned g_done;                // completion counter (self-resets)

__device__ __forceinline__ unsigned vload(const unsigned* p) {
    return *(volatile const unsigned*)p;
}

// Route: argmax + per-warp hist + block scan -> publish hist -> resident-grid
// barrier -> bulk prefix per warp -> order-preserving positions -> slot map.
// PLC trigger at the VERY END (after all writes + fence): PDL flush covers
// everything, no ordering hazard.
__global__ __launch_bounds__(TPB, 4) void k_route(const float* __restrict__ score) {
    __shared__ int sh_cnt[NWARP][PATHS];
    __shared__ int sh_wexcl[NWARP][PATHS];
    __shared__ int sh_excl[PATHS];
    __shared__ int sh_run[NWARP][PATHS];
    __shared__ int sh_last;
    const int tid = threadIdx.x, w = tid >> 5, lane = tid & 31, bid = blockIdx.x;
    const int tok = bid * TPB + tid;                    // one token per thread

    // ---- phase 1: argmax + per-warp per-path counts ----
    if (lane < PATHS) sh_cnt[w][lane] = 0;
    __syncwarp();
    int best;
    {
        const float4* sc = (const float4*)(score + (size_t)tok * PATHS);
        float4 a = __ldcs(sc), b = __ldcs(sc + 1), c = __ldcs(sc + 2), d = __ldcs(sc + 3);
        float v[16] = {a.x,a.y,a.z,a.w, b.x,b.y,b.z,b.w,
                       c.x,c.y,c.z,c.w, d.x,d.y,d.z,d.w};
        best = 0; float bv = v[0];
        #pragma unroll
        for (int p = 1; p < 16; p++) if (v[p] > bv) { bv = v[p]; best = p; }  // first-max
        unsigned m = __match_any_sync(0xffffffffu, best);
        if ((__ffs(m) - 1) == lane) sh_cnt[w][best] += __popc(m);
    }
    __syncthreads();

    // ---- block scan over 16 warps + publish block aggregate ----
    if (w == 0 && lane < PATHS) {
        int run = 0;
        #pragma unroll
        for (int ww = 0; ww < NWARP; ww++) { int v = sh_cnt[ww][lane]; sh_wexcl[ww][lane] = run; run += v; }
        g_hist[lane * NB + bid] = run;                  // [path][block]
        __threadfence();
    }
    __syncthreads();

    // ---- resident-grid barrier (all NB blocks co-resident by construction) ----
    if (tid == 0) {
        atomicAdd(&g_arrive, 1u);
        while (vload(&g_arrive) < (unsigned)NB) { }
    }
    __syncthreads();

    // ---- bulk prefix: warp w owns path w; read full hist row from L2 ----
    {
        int excl = 0, tot = 0;
        #pragma unroll
        for (int s = 0; s < NB / 32; s++) {
            const int j = s * 32 + lane;
            const int v = g_hist[w * NB + j];
            tot += v;
            if (j < bid) excl += v;
        }
        excl = __reduce_add_sync(0xffffffffu, excl);
        tot  = __reduce_add_sync(0xffffffffu, tot);
        if (lane == 0) {
            sh_excl[w] = excl;
            if (bid == 0) g_cnt[w] = tot < CAP ? tot : CAP;
        }
    }
    __syncthreads();

    // ---- order-preserving rank -> slot map ----
    if (lane < PATHS) sh_run[w][lane] = sh_excl[lane] + sh_wexcl[w][lane];
    __syncwarp();
    {
        unsigned m = __match_any_sync(0xffffffffu, best);
        const int rank = __popc(m & ((1u << lane) - 1u));
        const int pos = sh_run[w][best] + rank;
        if (pos < CAP) g_slot[best * CAP + pos] = tok;
    }

    // ---- self-clean + SAFE PDL trigger (all writes done + fenced) ----
    __threadfence();
    __syncthreads();
    if (tid == 0) sh_last = (atomicAdd(&g_done, 1u) == (unsigned)(NB - 1));
    __syncthreads();
    if (sh_last && tid == 0) { g_arrive = 0; g_done = 0; }
#if __CUDA_ARCH__ >= 900
    cudaTriggerProgrammaticLaunchCompletion();
#endif
}

// Gather: one warp per TWO output rows -> 8 independent float4 loads in flight
// (MLP=8) before any store. Grid 8192 x 512.
#define GROWS_PB 32
__global__ __launch_bounds__(512) void k_gather(const float4* __restrict__ in4,
                                                float4* __restrict__ out4) {
#if __CUDA_ARCH__ >= 900
    cudaGridDependencySynchronize();                    // PDL: wait for k_route
#endif
    const int w = threadIdx.x >> 5, lane = threadIdx.x & 31;
    const int rA = blockIdx.x * GROWS_PB + w;           // first row of this warp
    const int rB = rA + 16;                             // second row
    const int pA = rA >> 14, jA = rA & (CAP - 1);
    const int pB = rB >> 14, jB = rB & (CAP - 1);

    float4 a0 = make_float4(0.f,0.f,0.f,0.f);
    float4 a1 = a0, a2 = a0, a3 = a0;
    float4 b0 = a0, b1 = a0, b2 = a0, b3 = a0;
    const bool cA = (jA < g_cnt[pA]);
    const bool cB = (jB < g_cnt[pB]);
    if (cA) {
        const float4* src = in4 + (size_t)g_slot[rA] * D4 + lane;
        a0 = src[0]; a1 = src[32]; a2 = src[64]; a3 = src[96];
    }
    if (cB) {
        const float4* src = in4 + (size_t)g_slot[rB] * D4 + lane;
        b0 = src[0]; b1 = src[32]; b2 = src[64]; b3 = src[96];
    }
    float4* dA = out4 + (size_t)rA * D4 + lane;
    float4* dB = out4 + (size_t)rB * D4 + lane;
    dA[0]  = a0; dA[32] = a1; dA[64] = a2; dA[96] = a3;
    dB[0]  = b0; dB[32] = b1; dB[64] = b2; dB[96] = b3;
}

extern "C" void kernel_launch(void* const* d_in, const int* in_sizes, int n_in,
                              void* d_out, int out_size) {
    const float* inputs = (const float*)d_in[0];
    const float* score  = (const float*)d_in[1];
    if (in_sizes[0] == N_TOKENS * PATHS) {   // defensive: identify by element count
        inputs = (const float*)d_in[1];
        score  = (const float*)d_in[0];
    }
    k_route<<<NB, TPB>>>(score);

    cudaLaunchConfig_t cfg = {};
    cfg.gridDim  = dim3(ROWS / GROWS_PB, 1, 1);
    cfg.blockDim = dim3(512, 1, 1);
    cfg.stream   = 0;
    cudaLaunchAttribute attr[1];
    attr[0].id = cudaLaunchAttributeProgrammaticStreamSerialization;
    attr[0].val.programmaticStreamSerializationAllowed = 1;
    cfg.attrs = attr;
    cfg.numAttrs = 1;
    cudaLaunchKernelEx(&cfg, k_gather, (const float4*)inputs, (float4*)d_out);
}

// round 14
// speedup vs baseline: 1.1396x; 1.0078x over previous
#include <cuda_runtime.h>
#include <stdint.h>

#define N_TOKENS 131072
#define D_MODEL  512
#define PATHS    16
#define CAP      16384                 // 2 * N / P
#define D4       (D_MODEL / 4)         // 128 float4 per row
#define ROWS     (PATHS * CAP)         // 262144 output rows

#define NB       256                   // route blocks (all co-resident: 512thr)
#define TPB      512                   // 16 warps, one token per thread
#define NWARP    16

// ---- scratch (no allocations allowed; zero-initialized at load) ----
__device__ int      g_cnt[PATHS];          // per-path count, clamped to CAP
__device__ int      g_slot[ROWS];          // slot -> token gather map
__device__ int      g_hist[PATHS * NB];    // per-(path, block) counts  [path][block]
__device__ unsigned g_arrive;              // grid barrier counter (self-resets)
__device__ unsigned g_done;                // completion counter (self-resets)

__device__ __forceinline__ unsigned vload(const unsigned* p) {
    return *(volatile const unsigned*)p;
}

// Route: argmax + per-warp hist + block scan -> publish hist -> resident-grid
// barrier -> bulk prefix per warp -> order-preserving positions -> slot map.
// PLC trigger at the VERY END (after all writes + fence): PDL's flush covers
// every byte the gather reads.
__global__ __launch_bounds__(TPB, 4) void k_route(const float* __restrict__ score) {
    __shared__ int sh_cnt[NWARP][PATHS];
    __shared__ int sh_wexcl[NWARP][PATHS];
    __shared__ int sh_excl[PATHS];
    __shared__ int sh_run[NWARP][PATHS];
    __shared__ int sh_last;
    const int tid = threadIdx.x, w = tid >> 5, lane = tid & 31, bid = blockIdx.x;
    const int tok = bid * TPB + tid;                    // one token per thread

    // ---- phase 1: argmax + per-warp per-path counts ----
    if (lane < PATHS) sh_cnt[w][lane] = 0;
    __syncwarp();
    int best;
    {
        const float4* sc = (const float4*)(score + (size_t)tok * PATHS);
        float4 a = __ldcs(sc), b = __ldcs(sc + 1), c = __ldcs(sc + 2), d = __ldcs(sc + 3);
        float v[16] = {a.x,a.y,a.z,a.w, b.x,b.y,b.z,b.w,
                       c.x,c.y,c.z,c.w, d.x,d.y,d.z,d.w};
        best = 0; float bv = v[0];
        #pragma unroll
        for (int p = 1; p < 16; p++) if (v[p] > bv) { bv = v[p]; best = p; }  // first-max
        unsigned m = __match_any_sync(0xffffffffu, best);
        if ((__ffs(m) - 1) == lane) sh_cnt[w][best] += __popc(m);
    }
    __syncthreads();

    // ---- block scan over 16 warps + publish block aggregate ----
    if (w == 0 && lane < PATHS) {
        int run = 0;
        #pragma unroll
        for (int ww = 0; ww < NWARP; ww++) { int v = sh_cnt[ww][lane]; sh_wexcl[ww][lane] = run; run += v; }
        g_hist[lane * NB + bid] = run;                  // [path][block]
        __threadfence();
    }
    __syncthreads();

    // ---- resident-grid barrier (all NB blocks co-resident by construction) ----
    if (tid == 0) {
        atomicAdd(&g_arrive, 1u);
        while (vload(&g_arrive) < (unsigned)NB) { }
    }
    __syncthreads();

    // ---- bulk prefix: warp w owns path w; read full hist row from L2 ----
    {
        int excl = 0, tot = 0;
        #pragma unroll
        for (int s = 0; s < NB / 32; s++) {
            const int j = s * 32 + lane;
            const int v = g_hist[w * NB + j];
            tot += v;
            if (j < bid) excl += v;
        }
        excl = __reduce_add_sync(0xffffffffu, excl);
        tot  = __reduce_add_sync(0xffffffffu, tot);
        if (lane == 0) {
            sh_excl[w] = excl;
            if (bid == 0) g_cnt[w] = tot < CAP ? tot : CAP;
        }
    }
    __syncthreads();

    // ---- order-preserving rank -> slot map ----
    if (lane < PATHS) sh_run[w][lane] = sh_excl[lane] + sh_wexcl[w][lane];
    __syncwarp();
    {
        unsigned m = __match_any_sync(0xffffffffu, best);
        const int rank = __popc(m & ((1u << lane) - 1u));
        const int pos = sh_run[w][best] + rank;
        if (pos < CAP) g_slot[best * CAP + pos] = tok;
    }

    // ---- self-clean + SAFE PDL trigger (all writes done + fenced) ----
    __threadfence();
    __syncthreads();
    if (tid == 0) sh_last = (atomicAdd(&g_done, 1u) == (unsigned)(NB - 1));
    __syncthreads();
    if (sh_last && tid == 0) { g_arrive = 0; g_done = 0; }
#if __CUDA_ARCH__ >= 900
    cudaTriggerProgrammaticLaunchCompletion();
#endif
}

// Gather: one warp per output row, 4 independent float4s per lane (MLP=4).
// Measured optimum: 512 thr, 16384 blocks, regs 26, ~6.3 TB/s.
#define GROWS_PB 16
__global__ __launch_bounds__(512) void k_gather(const float4* __restrict__ in4,
                                                float4* __restrict__ out4) {
#if __CUDA_ARCH__ >= 900
    cudaGridDependencySynchronize();                    // PDL: wait for k_route
#endif
    const int w = threadIdx.x >> 5, lane = threadIdx.x & 31;
    const int r = blockIdx.x * GROWS_PB + w;            // output row in [0, ROWS)
    const int p = r >> 14;                              // r / CAP
    const int j = r & (CAP - 1);                        // r % CAP
    float4 v0 = make_float4(0.f,0.f,0.f,0.f);
    float4 v1 = v0, v2 = v0, v3 = v0;
    if (j < g_cnt[p]) {
        const float4* src = in4 + (size_t)g_slot[r] * D4 + lane;
        v0 = src[0];
        v1 = src[32];
        v2 = src[64];
        v3 = src[96];
    }
    float4* dst = out4 + (size_t)r * D4 + lane;
    dst[0]  = v0;
    dst[32] = v1;
    dst[64] = v2;
    dst[96] = v3;
}

extern "C" void kernel_launch(void* const* d_in, const int* in_sizes, int n_in,
                              void* d_out, int out_size) {
    const float* inputs = (const float*)d_in[0];
    const float* score  = (const float*)d_in[1];
    if (in_sizes[0] == N_TOKENS * PATHS) {   // defensive: identify by element count
        inputs = (const float*)d_in[1];
        score  = (const float*)d_in[0];
    }
    k_route<<<NB, TPB>>>(score);

    cudaLaunchConfig_t cfg = {};
    cfg.gridDim  = dim3(ROWS / GROWS_PB, 1, 1);
    cfg.blockDim = dim3(512, 1, 1);
    cfg.stream   = 0;
    cudaLaunchAttribute attr[1];
    attr[0].id = cudaLaunchAttributeProgrammaticStreamSerialization;
    attr[0].val.programmaticStreamSerializationAllowed = 1;
    cfg.attrs = attr;
    cfg.numAttrs = 1;
    cudaLaunchKernelEx(&cfg, k_gather, (const float4*)inputs, (float4*)d_out);
}

// round 15
// speedup vs baseline: 1.1508x; 1.0098x over previous
#include <cuda_runtime.h>
#include <stdint.h>

#define N_TOKENS 131072
#define D_MODEL  512
#define PATHS    16
#define CAP      16384                 // 2 * N / P
#define D4       (D_MODEL / 4)         // 128 float4 per row
#define ROWS     (PATHS * CAP)         // 262144 output rows

#define NB       256                   // route blocks (all co-resident: 512thr)
#define TPB      512                   // 16 warps, one token per thread
#define NWARP    16

// ---- scratch (no allocations allowed; zero-initialized at load) ----
__device__ int      g_cnt[PATHS];          // per-path count, clamped to CAP
__device__ int      g_slot[ROWS];          // slot -> token gather map
__device__ int      g_hist[PATHS * NB];    // per-(path, block) counts  [path][block]
__device__ unsigned g_arrive;              // grid barrier counter (self-resets)
__device__ unsigned g_done;                // completion counter (self-resets)

__device__ __forceinline__ unsigned vload(const unsigned* p) {
    return *(volatile const unsigned*)p;
}

// Route: argmax + per-warp hist + block scan -> publish hist -> resident-grid
// barrier -> bulk prefix per warp -> order-preserving positions -> slot map.
// PLC trigger fires right after this block's gather-visible writes are fenced
// (g_cnt + g_slot); the self-clean bookkeeping (not read by the gather) stays
// after the trigger, off the PLC critical path.
__global__ __launch_bounds__(TPB, 4) void k_route(const float* __restrict__ score) {
    __shared__ int sh_cnt[NWARP][PATHS];
    __shared__ int sh_wexcl[NWARP][PATHS];
    __shared__ int sh_excl[PATHS];
    __shared__ int sh_run[NWARP][PATHS];
    __shared__ int sh_last;
    const int tid = threadIdx.x, w = tid >> 5, lane = tid & 31, bid = blockIdx.x;
    const int tok = bid * TPB + tid;                    // one token per thread

    // ---- phase 1: argmax + per-warp per-path counts ----
    if (lane < PATHS) sh_cnt[w][lane] = 0;
    __syncwarp();
    int best;
    {
        const float4* sc = (const float4*)(score + (size_t)tok * PATHS);
        float4 a = __ldcs(sc), b = __ldcs(sc + 1), c = __ldcs(sc + 2), d = __ldcs(sc + 3);
        float v[16] = {a.x,a.y,a.z,a.w, b.x,b.y,b.z,b.w,
                       c.x,c.y,c.z,c.w, d.x,d.y,d.z,d.w};
        best = 0; float bv = v[0];
        #pragma unroll
        for (int p = 1; p < 16; p++) if (v[p] > bv) { bv = v[p]; best = p; }  // first-max
        unsigned m = __match_any_sync(0xffffffffu, best);
        if ((__ffs(m) - 1) == lane) sh_cnt[w][best] += __popc(m);
    }
    __syncthreads();

    // ---- block scan over 16 warps + publish block aggregate ----
    if (w == 0 && lane < PATHS) {
        int run = 0;
        #pragma unroll
        for (int ww = 0; ww < NWARP; ww++) { int v = sh_cnt[ww][lane]; sh_wexcl[ww][lane] = run; run += v; }
        g_hist[lane * NB + bid] = run;                  // [path][block]
        __threadfence();
    }
    __syncthreads();

    // ---- resident-grid barrier (all NB blocks co-resident by construction) ----
    if (tid == 0) {
        atomicAdd(&g_arrive, 1u);
        while (vload(&g_arrive) < (unsigned)NB) { }
    }
    __syncthreads();

    // ---- bulk prefix: warp w owns path w; read full hist row from L2 ----
    {
        int excl = 0, tot = 0;
        #pragma unroll
        for (int s = 0; s < NB / 32; s++) {
            const int j = s * 32 + lane;
            const int v = g_hist[w * NB + j];
            tot += v;
            if (j < bid) excl += v;
        }
        excl = __reduce_add_sync(0xffffffffu, excl);
        tot  = __reduce_add_sync(0xffffffffu, tot);
        if (lane == 0) {
            sh_excl[w] = excl;
            if (bid == 0) g_cnt[w] = tot < CAP ? tot : CAP;
        }
    }
    __syncthreads();

    // ---- order-preserving rank -> slot map ----
    if (lane < PATHS) sh_run[w][lane] = sh_excl[lane] + sh_wexcl[w][lane];
    __syncwarp();
    {
        unsigned m = __match_any_sync(0xffffffffu, best);
        const int rank = __popc(m & ((1u << lane) - 1u));
        const int pos = sh_run[w][best] + rank;
        if (pos < CAP) g_slot[best * CAP + pos] = tok;
    }

    // ---- all gather-visible writes (g_cnt, g_slot) done: fence, then trigger ----
    __threadfence();
    __syncthreads();
#if __CUDA_ARCH__ >= 900
    cudaTriggerProgrammaticLaunchCompletion();
#endif

    // ---- self-clean (next-replay state only; gather never reads these) ----
    if (tid == 0) sh_last = (atomicAdd(&g_done, 1u) == (unsigned)(NB - 1));
    __syncthreads();
    if (sh_last && tid == 0) { g_arrive = 0; g_done = 0; }
}

// Gather: one warp per output row, 4 independent float4s per lane (MLP=4).
// Measured optimum: 512 thr, 16384 blocks, regs 26, ~6.3 TB/s.
#define GROWS_PB 16
__global__ __launch_bounds__(512) void k_gather(const float4* __restrict__ in4,
                                                float4* __restrict__ out4) {
#if __CUDA_ARCH__ >= 900
    cudaGridDependencySynchronize();                    // PDL: wait for k_route
#endif
    const int w = threadIdx.x >> 5, lane = threadIdx.x & 31;
    const int r = blockIdx.x * GROWS_PB + w;            // output row in [0, ROWS)
    const int p = r >> 14;                              // r / CAP
    const int j = r & (CAP - 1);                        // r % CAP
    float4 v0 = make_float4(0.f,0.f,0.f,0.f);
    float4 v1 = v0, v2 = v0, v3 = v0;
    if (j < g_cnt[p]) {
        const float4* src = in4 + (size_t)g_slot[r] * D4 + lane;
        v0 = src[0];
        v1 = src[32];
        v2 = src[64];
        v3 = src[96];
    }
    float4* dst = out4 + (size_t)r * D4 + lane;
    dst[0]  = v0;
    dst[32] = v1;
    dst[64] = v2;
    dst[96] = v3;
}

extern "C" void kernel_launch(void* const* d_in, const int* in_sizes, int n_in,
                              void* d_out, int out_size) {
    const float* inputs = (const float*)d_in[0];
    const float* score  = (const float*)d_in[1];
    if (in_sizes[0] == N_TOKENS * PATHS) {   // defensive: identify by element count
        inputs = (const float*)d_in[1];
        score  = (const float*)d_in[0];
    }
    k_route<<<NB, TPB>>>(score);

    cudaLaunchConfig_t cfg = {};
    cfg.gridDim  = dim3(ROWS / GROWS_PB, 1, 1);
    cfg.blockDim = dim3(512, 1, 1);
    cfg.stream   = 0;
    cudaLaunchAttribute attr[1];
    attr[0].id = cudaLaunchAttributeProgrammaticStreamSerialization;
    attr[0].val.programmaticStreamSerializationAllowed = 1;
    cfg.attrs = attr;
    cfg.numAttrs = 1;
    cudaLaunchKernelEx(&cfg, k_gather, (const float4*)inputs, (float4*)d_out);
}